// round 1
// baseline (speedup 1.0000x reference)
#include <cuda_runtime.h>
#include <cstdint>

#define N_USERS 200000
#define N_EDGES 3200000
#define DIM 64
#define DV4 16   // DIM/4 float4 per row
#define ROWS_V4 (N_USERS * DV4)   // 3,200,000 float4 per buffer

// Ping-pong scratch for layer outputs (allocation-free rule: __device__ globals)
__device__ float4 g_scratch0[ROWS_V4];
__device__ float4 g_scratch1[ROWS_V4];

// ---------------------------------------------------------------------------
// out = in   (used to init accumulator with user_emb)
__global__ void k_copy(const float4* __restrict__ in, float4* __restrict__ out, int n) {
    int i = blockIdx.x * blockDim.x + threadIdx.x;
    if (i < n) out[i] = in[i];
}

// buf = 0
__global__ void k_zero(float4* __restrict__ buf, int n) {
    int i = blockIdx.x * blockDim.x + threadIdx.x;
    if (i < n) buf[i] = make_float4(0.f, 0.f, 0.f, 0.f);
}

// acc += h
__global__ void k_add(float4* __restrict__ acc, const float4* __restrict__ h, int n) {
    int i = blockIdx.x * blockDim.x + threadIdx.x;
    if (i < n) {
        float4 a = acc[i], b = h[i];
        a.x += b.x; a.y += b.y; a.z += b.z; a.w += b.w;
        acc[i] = a;
    }
}

// acc = (acc + h) * 0.25f   (final layer fused with the 1/(L+1) mean)
__global__ void k_add_scale(float4* __restrict__ acc, const float4* __restrict__ h, int n) {
    int i = blockIdx.x * blockDim.x + threadIdx.x;
    if (i < n) {
        float4 a = acc[i], b = h[i];
        a.x = (a.x + b.x) * 0.25f;
        a.y = (a.y + b.y) * 0.25f;
        a.z = (a.z + b.z) * 0.25f;
        a.w = (a.w + b.w) * 0.25f;
        acc[i] = a;
    }
}

// ---------------------------------------------------------------------------
// SpMM: out[dst[e]] += vals[e] * x[src[e]], 16 threads per edge (one float4 each).
// Vectorized no-return reduction (red.global.add.v4.f32).
__global__ void k_spmm(const float4* __restrict__ x,
                       const float*  __restrict__ vals,
                       const int*    __restrict__ src,
                       const int*    __restrict__ dst,
                       float4*       __restrict__ out,
                       int n_edges) {
    int t = blockIdx.x * blockDim.x + threadIdx.x;
    int e = t >> 4;          // edge index
    int c = t & 15;          // float4 component within the 64-dim row
    if (e >= n_edges) return;

    float v = __ldg(&vals[e]);
    int s = __ldg(&src[e]);
    int d = __ldg(&dst[e]);

    float4 xv = __ldg(&x[s * DV4 + c]);
    float4 m;
    m.x = v * xv.x; m.y = v * xv.y; m.z = v * xv.z; m.w = v * xv.w;

    float4* p = out + (d * DV4 + c);
    asm volatile("red.global.add.v4.f32 [%0], {%1, %2, %3, %4};"
                 :: "l"(p), "f"(m.x), "f"(m.y), "f"(m.z), "f"(m.w)
                 : "memory");
}

// ---------------------------------------------------------------------------
extern "C" void kernel_launch(void* const* d_in, const int* in_sizes, int n_in,
                              void* d_out, int out_size) {
    const float4* user_emb = (const float4*)d_in[0];   // [N_USERS, 64] f32
    const float*  edge_vals = (const float*)d_in[1];   // [E]
    const int*    edge_src  = (const int*)d_in[2];     // [E]
    const int*    edge_dst  = (const int*)d_in[3];     // [E]
    float4* acc = (float4*)d_out;                      // [N_USERS, 64] f32

    float4* s0;
    float4* s1;
    cudaGetSymbolAddress((void**)&s0, g_scratch0);
    cudaGetSymbolAddress((void**)&s1, g_scratch1);

    const int n_rows_v4 = ROWS_V4;
    const int VB = 256;
    const int vgrid = (n_rows_v4 + VB - 1) / VB;

    const int EB = 256;
    const long long ethreads = (long long)N_EDGES * 16;
    const int egrid = (int)((ethreads + EB - 1) / EB);

    // acc = user_emb
    k_copy<<<vgrid, VB>>>(user_emb, acc, n_rows_v4);

    // layer 1: s0 = G @ user_emb ; acc += s0
    k_zero<<<vgrid, VB>>>(s0, n_rows_v4);
    k_spmm<<<egrid, EB>>>(user_emb, edge_vals, edge_src, edge_dst, s0, N_EDGES);
    k_add<<<vgrid, VB>>>(acc, s0, n_rows_v4);

    // layer 2: s1 = G @ s0 ; acc += s1
    k_zero<<<vgrid, VB>>>(s1, n_rows_v4);
    k_spmm<<<egrid, EB>>>(s0, edge_vals, edge_src, edge_dst, s1, N_EDGES);
    k_add<<<vgrid, VB>>>(acc, s1, n_rows_v4);

    // layer 3: s0 = G @ s1 ; acc = (acc + s0) / 4
    k_zero<<<vgrid, VB>>>(s0, n_rows_v4);
    k_spmm<<<egrid, EB>>>(s1, edge_vals, edge_src, edge_dst, s0, N_EDGES);
    k_add_scale<<<vgrid, VB>>>(acc, s0, n_rows_v4);
}

// round 3
// speedup vs baseline: 1.8526x; 1.8526x over previous
#include <cuda_runtime.h>
#include <cstdint>

#define N_USERS 200000
#define N_EDGES 3200000
#define DIM 64
#define DV4 16
#define ROWS_V4 (N_USERS * DV4)     // 3,200,000 float4 per buffer
#define SCAN_B 1024
#define N_SCAN_BLOCKS ((N_USERS + SCAN_B - 1) / SCAN_B)   // 196

// ---- static scratch (allocation-free rule) --------------------------------
__device__ float4 g_h0[ROWS_V4];            // 51.2 MB  layer output ping
__device__ float4 g_h1[ROWS_V4];            // 51.2 MB  layer output pong
__device__ int2   g_perm[N_EDGES];          // 25.6 MB  packed (src, val) grouped by dst
__device__ int    g_counts[N_USERS];
__device__ int    g_row_start[N_USERS];
__device__ int    g_row_fill[N_USERS];
__device__ int    g_partial[N_USERS];
__device__ int    g_block_sums[N_SCAN_BLOCKS];
__device__ int    g_block_offs[N_SCAN_BLOCKS];

// ---------------------------------------------------------------------------
__global__ void k_zero_counts(int* counts, int n) {
    int i = blockIdx.x * blockDim.x + threadIdx.x;
    if (i < n) counts[i] = 0;
}

__global__ void k_hist(const int* __restrict__ dst, int* counts, int n) {
    int i = blockIdx.x * blockDim.x + threadIdx.x;
    if (i < n) atomicAdd(&counts[dst[i]], 1);
}

// block-level exclusive scan; writes per-block totals
__global__ void k_scan1(const int* __restrict__ counts, int* partial,
                        int* block_sums, int n) {
    __shared__ int sh[SCAN_B];
    int i = blockIdx.x * SCAN_B + threadIdx.x;
    int v = (i < n) ? counts[i] : 0;
    sh[threadIdx.x] = v;
    __syncthreads();
    #pragma unroll
    for (int off = 1; off < SCAN_B; off <<= 1) {
        int t = (threadIdx.x >= off) ? sh[threadIdx.x - off] : 0;
        __syncthreads();
        sh[threadIdx.x] += t;
        __syncthreads();
    }
    if (i < n) partial[i] = sh[threadIdx.x] - v;     // exclusive
    if (threadIdx.x == SCAN_B - 1) block_sums[blockIdx.x] = sh[SCAN_B - 1];
}

// single-block exclusive scan of the 196 block sums
__global__ void k_scan2(const int* __restrict__ block_sums, int* block_offs, int n) {
    __shared__ int sh[SCAN_B];
    int v = (threadIdx.x < n) ? block_sums[threadIdx.x] : 0;
    sh[threadIdx.x] = v;
    __syncthreads();
    #pragma unroll
    for (int off = 1; off < SCAN_B; off <<= 1) {
        int t = (threadIdx.x >= off) ? sh[threadIdx.x - off] : 0;
        __syncthreads();
        sh[threadIdx.x] += t;
        __syncthreads();
    }
    if (threadIdx.x < n) block_offs[threadIdx.x] = sh[threadIdx.x] - v;
}

__global__ void k_scan3(const int* __restrict__ partial,
                        const int* __restrict__ block_offs,
                        int* row_start, int* row_fill, int n) {
    int i = blockIdx.x * blockDim.x + threadIdx.x;
    if (i < n) {
        int s = partial[i] + block_offs[i / SCAN_B];
        row_start[i] = s;
        row_fill[i]  = s;
    }
}

__global__ void k_scatter(const float* __restrict__ vals,
                          const int* __restrict__ src,
                          const int* __restrict__ dst,
                          int* row_fill, int2* perm, int n) {
    int e = blockIdx.x * blockDim.x + threadIdx.x;
    if (e < n) {
        int d = dst[e];
        int pos = atomicAdd(&row_fill[d], 1);
        perm[pos] = make_int2(src[e], __float_as_int(vals[e]));
    }
}

// ---------------------------------------------------------------------------
// Pull-mode SpMM: 16 lanes per row, lane c owns float4 column c.
// MODE 0: h_out = G@x ;  acc = emb + h_out                 (layer 1)
// MODE 1: h_out = G@x ;  acc += h_out                      (layer 2)
// MODE 2: acc = (acc + G@x) * 0.25 ; no h_out write        (layer 3)
template <int MODE>
__global__ void __launch_bounds__(256)
k_spmm_csr(const float4* __restrict__ x,
           const int2*  __restrict__ perm,
           const int*   __restrict__ row_start,
           const int*   __restrict__ counts,
           float4*      __restrict__ h_out,
           float4*      __restrict__ acc,
           const float4* __restrict__ emb) {
    int t = blockIdx.x * blockDim.x + threadIdx.x;
    int row = t >> 4;
    int c   = t & 15;
    if (row >= N_USERS) return;

    int beg = __ldg(&row_start[row]);
    int cnt = __ldg(&counts[row]);
    int end = beg + cnt;

    float4 a = make_float4(0.f, 0.f, 0.f, 0.f);

    // software-pipelined by 1: overlap next perm/x fetch with current FMA
    if (cnt > 0) {
        int2 p = __ldg(&perm[beg]);
        float4 xv = __ldg(&x[p.x * DV4 + c]);
        float v = __int_as_float(p.y);
        for (int j = beg + 1; j < end; ++j) {
            int2 pn = __ldg(&perm[j]);
            float4 xn = __ldg(&x[pn.x * DV4 + c]);
            a.x += v * xv.x; a.y += v * xv.y; a.z += v * xv.z; a.w += v * xv.w;
            v = __int_as_float(pn.y);
            xv = xn;
        }
        a.x += v * xv.x; a.y += v * xv.y; a.z += v * xv.z; a.w += v * xv.w;
    }

    int o = row * DV4 + c;
    if (MODE == 0) {
        h_out[o] = a;
        float4 e = __ldg(&emb[o]);
        acc[o] = make_float4(e.x + a.x, e.y + a.y, e.z + a.z, e.w + a.w);
    } else if (MODE == 1) {
        h_out[o] = a;
        float4 ac = acc[o];
        acc[o] = make_float4(ac.x + a.x, ac.y + a.y, ac.z + a.z, ac.w + a.w);
    } else {
        float4 ac = acc[o];
        acc[o] = make_float4((ac.x + a.x) * 0.25f, (ac.y + a.y) * 0.25f,
                             (ac.z + a.z) * 0.25f, (ac.w + a.w) * 0.25f);
    }
}

// ---------------------------------------------------------------------------
extern "C" void kernel_launch(void* const* d_in, const int* in_sizes, int n_in,
                              void* d_out, int out_size) {
    const float4* user_emb  = (const float4*)d_in[0];
    const float*  edge_vals = (const float*)d_in[1];
    const int*    edge_src  = (const int*)d_in[2];
    const int*    edge_dst  = (const int*)d_in[3];
    float4* acc = (float4*)d_out;

    float4 *h0, *h1;
    int2* perm;
    int *counts, *row_start, *row_fill, *partial, *bsums, *boffs;
    cudaGetSymbolAddress((void**)&h0, g_h0);
    cudaGetSymbolAddress((void**)&h1, g_h1);
    cudaGetSymbolAddress((void**)&perm, g_perm);
    cudaGetSymbolAddress((void**)&counts, g_counts);
    cudaGetSymbolAddress((void**)&row_start, g_row_start);
    cudaGetSymbolAddress((void**)&row_fill, g_row_fill);
    cudaGetSymbolAddress((void**)&partial, g_partial);
    cudaGetSymbolAddress((void**)&bsums, g_block_sums);
    cudaGetSymbolAddress((void**)&boffs, g_block_offs);

    const int EB = 256;
    const int egrid = (N_EDGES + EB - 1) / EB;              // 12500
    const int ugrid = (N_USERS + EB - 1) / EB;              // 782
    const int sgrid = (N_USERS * DV4 + EB - 1) / EB;        // 12500 (16 thr/row)

    // ---- CSR build ----
    k_zero_counts<<<ugrid, EB>>>(counts, N_USERS);
    k_hist<<<egrid, EB>>>(edge_dst, counts, N_EDGES);
    k_scan1<<<N_SCAN_BLOCKS, SCAN_B>>>(counts, partial, bsums, N_USERS);
    k_scan2<<<1, SCAN_B>>>(bsums, boffs, N_SCAN_BLOCKS);
    k_scan3<<<ugrid, EB>>>(partial, boffs, row_start, row_fill, N_USERS);
    k_scatter<<<egrid, EB>>>(edge_vals, edge_src, edge_dst, row_fill, perm, N_EDGES);

    // ---- 3 propagation layers, elementwise work fused into epilogues ----
    k_spmm_csr<0><<<sgrid, EB>>>(user_emb, perm, row_start, counts, h0, acc, user_emb);
    k_spmm_csr<1><<<sgrid, EB>>>(h0,       perm, row_start, counts, h1, acc, nullptr);
    k_spmm_csr<2><<<sgrid, EB>>>(h1,       perm, row_start, counts, nullptr, acc, nullptr);
}

// round 5
// speedup vs baseline: 2.2365x; 1.2072x over previous
#include <cuda_runtime.h>
#include <cstdint>

#define N_USERS 200000
#define N_EDGES 3200000
#define DIM 64
#define DV4 16
#define ROWS_V4 (N_USERS * DV4)
#define SCAN_B 1024
#define N_SCAN_BLOCKS ((N_USERS + SCAN_B - 1) / SCAN_B)   // 196

// ---- static scratch (allocation-free rule) --------------------------------
__device__ float4 g_h0[ROWS_V4];            // 51.2 MB
__device__ float4 g_h1[ROWS_V4];            // 51.2 MB
__device__ int2   g_perm[N_EDGES];          // 25.6 MB packed (src, val) grouped by dst
__device__ int    g_counts[N_USERS];
__device__ int    g_row_start[N_USERS];
__device__ int    g_row_fill[N_USERS];      // post-scatter == row end
__device__ int    g_block_sums[N_SCAN_BLOCKS];

// ---------------------------------------------------------------------------
__global__ void k_zero_counts(int* counts, int n) {
    int i = blockIdx.x * blockDim.x + threadIdx.x;
    if (i < n) counts[i] = 0;
}

// histogram of dst, int4-vectorized (N_EDGES % 4 == 0)
__global__ void k_hist(const int4* __restrict__ dst4, int* counts, int n4) {
    int i = blockIdx.x * blockDim.x + threadIdx.x;
    if (i < n4) {
        int4 d = __ldg(&dst4[i]);
        atomicAdd(&counts[d.x], 1);
        atomicAdd(&counts[d.y], 1);
        atomicAdd(&counts[d.z], 1);
        atomicAdd(&counts[d.w], 1);
    }
}

// per-block reduce of counts -> block_sums
__global__ void k_block_reduce(const int* __restrict__ counts, int* block_sums, int n) {
    __shared__ int sh[SCAN_B];
    int i = blockIdx.x * SCAN_B + threadIdx.x;
    sh[threadIdx.x] = (i < n) ? counts[i] : 0;
    __syncthreads();
    #pragma unroll
    for (int off = SCAN_B / 2; off > 0; off >>= 1) {
        if (threadIdx.x < off) sh[threadIdx.x] += sh[threadIdx.x + off];
        __syncthreads();
    }
    if (threadIdx.x == 0) block_sums[blockIdx.x] = sh[0];
}

// fused scan: each block (a) redundantly prefix-sums the 196 block sums to get
// its global offset, (b) scans its own 1024 counts, (c) writes row_start/row_fill.
__global__ void k_scan_final(const int* __restrict__ counts,
                             const int* __restrict__ block_sums,
                             int* row_start, int* row_fill, int n) {
    __shared__ int shb[SCAN_B];
    __shared__ int shc[SCAN_B];
    // (a) scan block sums (196 valid, rest zero)
    shb[threadIdx.x] = (threadIdx.x < N_SCAN_BLOCKS) ? block_sums[threadIdx.x] : 0;
    __syncthreads();
    #pragma unroll
    for (int off = 1; off < SCAN_B; off <<= 1) {
        int t = (threadIdx.x >= off) ? shb[threadIdx.x - off] : 0;
        __syncthreads();
        shb[threadIdx.x] += t;
        __syncthreads();
    }
    int blk_off = (blockIdx.x > 0) ? shb[blockIdx.x - 1] : 0;   // exclusive

    // (b) scan own counts chunk
    int i = blockIdx.x * SCAN_B + threadIdx.x;
    int v = (i < n) ? counts[i] : 0;
    shc[threadIdx.x] = v;
    __syncthreads();
    #pragma unroll
    for (int off = 1; off < SCAN_B; off <<= 1) {
        int t = (threadIdx.x >= off) ? shc[threadIdx.x - off] : 0;
        __syncthreads();
        shc[threadIdx.x] += t;
        __syncthreads();
    }
    if (i < n) {
        int s = blk_off + shc[threadIdx.x] - v;   // exclusive
        row_start[i] = s;
        row_fill[i]  = s;
    }
}

// scatter edges into dst-grouped order, 4 edges per thread
__global__ void k_scatter(const float4* __restrict__ vals4,
                          const int4* __restrict__ src4,
                          const int4* __restrict__ dst4,
                          int* row_fill, int2* perm, int n4) {
    int i = blockIdx.x * blockDim.x + threadIdx.x;
    if (i >= n4) return;
    int4 s = __ldg(&src4[i]);
    int4 d = __ldg(&dst4[i]);
    float4 v = __ldg(&vals4[i]);
    int p;
    p = atomicAdd(&row_fill[d.x], 1); perm[p] = make_int2(s.x, __float_as_int(v.x));
    p = atomicAdd(&row_fill[d.y], 1); perm[p] = make_int2(s.y, __float_as_int(v.y));
    p = atomicAdd(&row_fill[d.z], 1); perm[p] = make_int2(s.z, __float_as_int(v.z));
    p = atomicAdd(&row_fill[d.w], 1); perm[p] = make_int2(s.w, __float_as_int(v.w));
}

// ---------------------------------------------------------------------------
// Pull-mode SpMM, 16 lanes per row, dual-accumulator (2 gather chains in flight).
// MODE 0/1: h_out = G@x
// MODE 2:   acc = (emb + h0 + h1 + G@x) * 0.25
template <int MODE>
__global__ void __launch_bounds__(256)
k_spmm_csr(const float4* __restrict__ x,
           const int2*  __restrict__ perm,
           const int*   __restrict__ row_start,
           const int*   __restrict__ row_end,
           float4*      __restrict__ h_out,
           float4*      __restrict__ acc,
           const float4* __restrict__ emb,
           const float4* __restrict__ h0,
           const float4* __restrict__ h1) {
    int t = blockIdx.x * blockDim.x + threadIdx.x;
    int row = t >> 4;
    int c   = t & 15;
    if (row >= N_USERS) return;

    int j   = __ldg(&row_start[row]);
    int end = __ldg(&row_end[row]);

    float4 a0 = make_float4(0.f, 0.f, 0.f, 0.f);
    float4 a1 = make_float4(0.f, 0.f, 0.f, 0.f);

    for (; j + 2 <= end; j += 2) {
        int2 p0 = __ldg(&perm[j]);
        int2 p1 = __ldg(&perm[j + 1]);
        float4 x0 = __ldg(&x[p0.x * DV4 + c]);
        float4 x1 = __ldg(&x[p1.x * DV4 + c]);
        float v0 = __int_as_float(p0.y);
        float v1 = __int_as_float(p1.y);
        a0.x += v0 * x0.x; a0.y += v0 * x0.y; a0.z += v0 * x0.z; a0.w += v0 * x0.w;
        a1.x += v1 * x1.x; a1.y += v1 * x1.y; a1.z += v1 * x1.z; a1.w += v1 * x1.w;
    }
    if (j < end) {
        int2 p = __ldg(&perm[j]);
        float4 xv = __ldg(&x[p.x * DV4 + c]);
        float v = __int_as_float(p.y);
        a0.x += v * xv.x; a0.y += v * xv.y; a0.z += v * xv.z; a0.w += v * xv.w;
    }
    float4 a = make_float4(a0.x + a1.x, a0.y + a1.y, a0.z + a1.z, a0.w + a1.w);

    int o = row * DV4 + c;
    if (MODE == 2) {
        float4 e  = __ldg(&emb[o]);
        float4 b0 = __ldg(&h0[o]);
        float4 b1 = __ldg(&h1[o]);
        acc[o] = make_float4((e.x + b0.x + b1.x + a.x) * 0.25f,
                             (e.y + b0.y + b1.y + a.y) * 0.25f,
                             (e.z + b0.z + b1.z + a.z) * 0.25f,
                             (e.w + b0.w + b1.w + a.w) * 0.25f);
    } else {
        h_out[o] = a;
    }
}

// ---------------------------------------------------------------------------
extern "C" void kernel_launch(void* const* d_in, const int* in_sizes, int n_in,
                              void* d_out, int out_size) {
    const float4* user_emb  = (const float4*)d_in[0];
    const float*  edge_vals = (const float*)d_in[1];
    const int*    edge_src  = (const int*)d_in[2];
    const int*    edge_dst  = (const int*)d_in[3];
    float4* acc = (float4*)d_out;

    float4 *h0, *h1;
    int2* perm;
    int *counts, *row_start, *row_fill, *bsums;
    cudaGetSymbolAddress((void**)&h0, g_h0);
    cudaGetSymbolAddress((void**)&h1, g_h1);
    cudaGetSymbolAddress((void**)&perm, g_perm);
    cudaGetSymbolAddress((void**)&counts, g_counts);
    cudaGetSymbolAddress((void**)&row_start, g_row_start);
    cudaGetSymbolAddress((void**)&row_fill, g_row_fill);
    cudaGetSymbolAddress((void**)&bsums, g_block_sums);

    const int EB = 256;
    const int n4 = N_EDGES / 4;
    const int e4grid = (n4 + EB - 1) / EB;
    const int ugrid  = (N_USERS + EB - 1) / EB;
    const int sgrid  = (N_USERS * DV4 + EB - 1) / EB;   // 16 threads/row

    // ---- CSR build (5 kernels) ----
    k_zero_counts<<<ugrid, EB>>>(counts, N_USERS);
    k_hist<<<e4grid, EB>>>((const int4*)edge_dst, counts, n4);
    k_block_reduce<<<N_SCAN_BLOCKS, SCAN_B>>>(counts, bsums, N_USERS);
    k_scan_final<<<N_SCAN_BLOCKS, SCAN_B>>>(counts, bsums, row_start, row_fill, N_USERS);
    k_scatter<<<e4grid, EB>>>((const float4*)edge_vals, (const int4*)edge_src,
                              (const int4*)edge_dst, row_fill, perm, n4);

    // ---- 3 propagation layers ----
    k_spmm_csr<0><<<sgrid, EB>>>(user_emb, perm, row_start, row_fill, h0,
                                 nullptr, nullptr, nullptr, nullptr);
    k_spmm_csr<1><<<sgrid, EB>>>(h0, perm, row_start, row_fill, h1,
                                 nullptr, nullptr, nullptr, nullptr);
    k_spmm_csr<2><<<sgrid, EB>>>(h1, perm, row_start, row_fill, nullptr,
                                 acc, user_emb, h0, h1);
}

// round 6
// speedup vs baseline: 2.8764x; 1.2862x over previous
#include <cuda_runtime.h>
#include <cuda_fp16.h>
#include <cstdint>

#define N_USERS 200000
#define N_EDGES 3200000
#define DIM 64
#define DV4 16                      // 16 chunks of 4 dims per row
#define ROWS_V4 (N_USERS * DV4)
#define SCAN_B 1024
#define N_SCAN_BLOCKS ((N_USERS + SCAN_B - 1) / SCAN_B)   // 196

// ---- static scratch (allocation-free rule) --------------------------------
// fp16 embedding buffers: 4 halves packed in a uint2 (8B) per 4-dim chunk.
__device__ uint2 g_x0h[ROWS_V4];            // 25.6 MB  fp16(user_emb)
__device__ uint2 g_h0h[ROWS_V4];            // 25.6 MB  fp16 layer-1 output
__device__ uint2 g_h1h[ROWS_V4];            // 25.6 MB  fp16 layer-2 output
__device__ int2  g_perm[N_EDGES];           // 25.6 MB  packed (src, val) grouped by dst
__device__ int   g_counts[N_USERS];
__device__ int   g_row_start[N_USERS];
__device__ int   g_row_fill[N_USERS];       // post-scatter == row end
__device__ int   g_block_sums[N_SCAN_BLOCKS];

// ---- fp16 pack/unpack helpers ---------------------------------------------
__device__ __forceinline__ float4 half4_to_float4(uint2 u) {
    __half2 a = *reinterpret_cast<__half2*>(&u.x);
    __half2 b = *reinterpret_cast<__half2*>(&u.y);
    float2 fa = __half22float2(a);
    float2 fb = __half22float2(b);
    return make_float4(fa.x, fa.y, fb.x, fb.y);
}
__device__ __forceinline__ uint2 float4_to_half4(float4 f) {
    __half2 a = __floats2half2_rn(f.x, f.y);
    __half2 b = __floats2half2_rn(f.z, f.w);
    uint2 u;
    u.x = *reinterpret_cast<uint32_t*>(&a);
    u.y = *reinterpret_cast<uint32_t*>(&b);
    return u;
}

// ---------------------------------------------------------------------------
__global__ void k_zero_counts(int* counts, int n) {
    int i = blockIdx.x * blockDim.x + threadIdx.x;
    if (i < n) counts[i] = 0;
}

__global__ void k_f2h(const float4* __restrict__ in, uint2* __restrict__ out, int n) {
    int i = blockIdx.x * blockDim.x + threadIdx.x;
    if (i < n) out[i] = float4_to_half4(__ldg(&in[i]));
}

// histogram of dst, int4-vectorized (N_EDGES % 4 == 0)
__global__ void k_hist(const int4* __restrict__ dst4, int* counts, int n4) {
    int i = blockIdx.x * blockDim.x + threadIdx.x;
    if (i < n4) {
        int4 d = __ldg(&dst4[i]);
        atomicAdd(&counts[d.x], 1);
        atomicAdd(&counts[d.y], 1);
        atomicAdd(&counts[d.z], 1);
        atomicAdd(&counts[d.w], 1);
    }
}

__global__ void k_block_reduce(const int* __restrict__ counts, int* block_sums, int n) {
    __shared__ int sh[SCAN_B];
    int i = blockIdx.x * SCAN_B + threadIdx.x;
    sh[threadIdx.x] = (i < n) ? counts[i] : 0;
    __syncthreads();
    #pragma unroll
    for (int off = SCAN_B / 2; off > 0; off >>= 1) {
        if (threadIdx.x < off) sh[threadIdx.x] += sh[threadIdx.x + off];
        __syncthreads();
    }
    if (threadIdx.x == 0) block_sums[blockIdx.x] = sh[0];
}

// fused scan: each block redundantly prefix-sums the 196 block sums for its
// global offset, scans its own 1024 counts, writes row_start/row_fill.
__global__ void k_scan_final(const int* __restrict__ counts,
                             const int* __restrict__ block_sums,
                             int* row_start, int* row_fill, int n) {
    __shared__ int shb[SCAN_B];
    __shared__ int shc[SCAN_B];
    shb[threadIdx.x] = (threadIdx.x < N_SCAN_BLOCKS) ? block_sums[threadIdx.x] : 0;
    __syncthreads();
    #pragma unroll
    for (int off = 1; off < SCAN_B; off <<= 1) {
        int t = (threadIdx.x >= off) ? shb[threadIdx.x - off] : 0;
        __syncthreads();
        shb[threadIdx.x] += t;
        __syncthreads();
    }
    int blk_off = (blockIdx.x > 0) ? shb[blockIdx.x - 1] : 0;   // exclusive

    int i = blockIdx.x * SCAN_B + threadIdx.x;
    int v = (i < n) ? counts[i] : 0;
    shc[threadIdx.x] = v;
    __syncthreads();
    #pragma unroll
    for (int off = 1; off < SCAN_B; off <<= 1) {
        int t = (threadIdx.x >= off) ? shc[threadIdx.x - off] : 0;
        __syncthreads();
        shc[threadIdx.x] += t;
        __syncthreads();
    }
    if (i < n) {
        int s = blk_off + shc[threadIdx.x] - v;   // exclusive
        row_start[i] = s;
        row_fill[i]  = s;
    }
}

// scatter edges into dst-grouped order, 4 edges per thread
__global__ void k_scatter(const float4* __restrict__ vals4,
                          const int4* __restrict__ src4,
                          const int4* __restrict__ dst4,
                          int* row_fill, int2* perm, int n4) {
    int i = blockIdx.x * blockDim.x + threadIdx.x;
    if (i >= n4) return;
    int4 s = __ldg(&src4[i]);
    int4 d = __ldg(&dst4[i]);
    float4 v = __ldg(&vals4[i]);
    int p;
    p = atomicAdd(&row_fill[d.x], 1); perm[p] = make_int2(s.x, __float_as_int(v.x));
    p = atomicAdd(&row_fill[d.y], 1); perm[p] = make_int2(s.y, __float_as_int(v.y));
    p = atomicAdd(&row_fill[d.z], 1); perm[p] = make_int2(s.z, __float_as_int(v.z));
    p = atomicAdd(&row_fill[d.w], 1); perm[p] = make_int2(s.w, __float_as_int(v.w));
}

// ---------------------------------------------------------------------------
// Pull-mode SpMM over fp16 embeddings, fp32 accumulation.
// 16 lanes per row, lane c owns dims [4c, 4c+4). Dual gather chains in flight.
// MODE 0/1: h_out = fp16(G@x)
// MODE 2:   acc = (emb + h0 + h1 + G@x) * 0.25   (fp32 out)
template <int MODE>
__global__ void __launch_bounds__(256)
k_spmm_half(const uint2* __restrict__ x,
            const int2*  __restrict__ perm,
            const int*   __restrict__ row_start,
            const int*   __restrict__ row_end,
            uint2*       __restrict__ h_out,
            float4*      __restrict__ acc,
            const float4* __restrict__ emb,
            const uint2* __restrict__ h0,
            const uint2* __restrict__ h1) {
    int t = blockIdx.x * blockDim.x + threadIdx.x;
    int row = t >> 4;
    int c   = t & 15;
    if (row >= N_USERS) return;

    int j   = __ldg(&row_start[row]);
    int end = __ldg(&row_end[row]);

    float4 a0 = make_float4(0.f, 0.f, 0.f, 0.f);
    float4 a1 = make_float4(0.f, 0.f, 0.f, 0.f);

    for (; j + 2 <= end; j += 2) {
        int2 p0 = __ldg(&perm[j]);
        int2 p1 = __ldg(&perm[j + 1]);
        uint2 u0 = __ldg(&x[p0.x * DV4 + c]);
        uint2 u1 = __ldg(&x[p1.x * DV4 + c]);
        float v0 = __int_as_float(p0.y);
        float v1 = __int_as_float(p1.y);
        float4 x0 = half4_to_float4(u0);
        float4 x1 = half4_to_float4(u1);
        a0.x += v0 * x0.x; a0.y += v0 * x0.y; a0.z += v0 * x0.z; a0.w += v0 * x0.w;
        a1.x += v1 * x1.x; a1.y += v1 * x1.y; a1.z += v1 * x1.z; a1.w += v1 * x1.w;
    }
    if (j < end) {
        int2 p = __ldg(&perm[j]);
        uint2 u = __ldg(&x[p.x * DV4 + c]);
        float v = __int_as_float(p.y);
        float4 xv = half4_to_float4(u);
        a0.x += v * xv.x; a0.y += v * xv.y; a0.z += v * xv.z; a0.w += v * xv.w;
    }
    float4 a = make_float4(a0.x + a1.x, a0.y + a1.y, a0.z + a1.z, a0.w + a1.w);

    int o = row * DV4 + c;
    if (MODE == 2) {
        float4 e  = __ldg(&emb[o]);
        float4 b0 = half4_to_float4(__ldg(&h0[o]));
        float4 b1 = half4_to_float4(__ldg(&h1[o]));
        acc[o] = make_float4((e.x + b0.x + b1.x + a.x) * 0.25f,
                             (e.y + b0.y + b1.y + a.y) * 0.25f,
                             (e.z + b0.z + b1.z + a.z) * 0.25f,
                             (e.w + b0.w + b1.w + a.w) * 0.25f);
    } else {
        h_out[o] = float4_to_half4(a);
    }
}

// ---------------------------------------------------------------------------
extern "C" void kernel_launch(void* const* d_in, const int* in_sizes, int n_in,
                              void* d_out, int out_size) {
    const float4* user_emb  = (const float4*)d_in[0];
    const float*  edge_vals = (const float*)d_in[1];
    const int*    edge_src  = (const int*)d_in[2];
    const int*    edge_dst  = (const int*)d_in[3];
    float4* acc = (float4*)d_out;

    uint2 *x0h, *h0h, *h1h;
    int2* perm;
    int *counts, *row_start, *row_fill, *bsums;
    cudaGetSymbolAddress((void**)&x0h, g_x0h);
    cudaGetSymbolAddress((void**)&h0h, g_h0h);
    cudaGetSymbolAddress((void**)&h1h, g_h1h);
    cudaGetSymbolAddress((void**)&perm, g_perm);
    cudaGetSymbolAddress((void**)&counts, g_counts);
    cudaGetSymbolAddress((void**)&row_start, g_row_start);
    cudaGetSymbolAddress((void**)&row_fill, g_row_fill);
    cudaGetSymbolAddress((void**)&bsums, g_block_sums);

    const int EB = 256;
    const int n4 = N_EDGES / 4;
    const int e4grid = (n4 + EB - 1) / EB;
    const int ugrid  = (N_USERS + EB - 1) / EB;
    const int sgrid  = (N_USERS * DV4 + EB - 1) / EB;   // 16 threads/row
    const int cgrid  = (ROWS_V4 + EB - 1) / EB;

    // ---- CSR build + fp16 conversion ----
    k_zero_counts<<<ugrid, EB>>>(counts, N_USERS);
    k_hist<<<e4grid, EB>>>((const int4*)edge_dst, counts, n4);
    k_block_reduce<<<N_SCAN_BLOCKS, SCAN_B>>>(counts, bsums, N_USERS);
    k_scan_final<<<N_SCAN_BLOCKS, SCAN_B>>>(counts, bsums, row_start, row_fill, N_USERS);
    k_scatter<<<e4grid, EB>>>((const float4*)edge_vals, (const int4*)edge_src,
                              (const int4*)edge_dst, row_fill, perm, n4);
    k_f2h<<<cgrid, EB>>>(user_emb, x0h, ROWS_V4);

    // ---- 3 propagation layers ----
    k_spmm_half<0><<<sgrid, EB>>>(x0h, perm, row_start, row_fill, h0h,
                                  nullptr, nullptr, nullptr, nullptr);
    k_spmm_half<1><<<sgrid, EB>>>(h0h, perm, row_start, row_fill, h1h,
                                  nullptr, nullptr, nullptr, nullptr);
    k_spmm_half<2><<<sgrid, EB>>>(h1h, perm, row_start, row_fill, nullptr,
                                  acc, user_emb, h0h, h1h);
}